// round 1
// baseline (speedup 1.0000x reference)
#include <cuda_runtime.h>
#include <math.h>
#include <float.h>

#define Bb 2
#define Ss 1024
#define DMm 1024
#define Hh 16
#define Dd 64
#define BH (Bb*Hh)        // 32
#define Ff (2*Dd)         // 128

// ---- scratch (static device globals; no allocation allowed) ----
__device__ float g_q[BH*Ss*Dd];     // 8 MB, head layout (b,h,s,d)
__device__ float g_k[BH*Ss*Dd];
__device__ float g_v[BH*Ss*Dd];
__device__ float g_fq[BH*Ss*Ff];    // 16 MB
__device__ float g_fk[BH*Ss*Ff];
__device__ float g_ctx[BH*Ss*Dd];

// out layout: [outputs (B*S*DM)] [pred_attns (B*H*S*S)] [true_attns (B*H*S*S)]
#define OFF_PRED (Bb*Ss*DMm)
#define OFF_TRUE (OFF_PRED + BH*Ss*Ss)

// ============================================================
// Kernel 1: QKV projection.  y = X @ W^T + b, write head layout.
// BM=128, BN=64, BK=32, 256 threads, 8x4 per thread.
// ============================================================
__global__ __launch_bounds__(256) void qkv_kernel(
    const float* __restrict__ X,
    const float* __restrict__ Wq, const float* __restrict__ bq,
    const float* __restrict__ Wk, const float* __restrict__ bk,
    const float* __restrict__ Wv, const float* __restrict__ bv)
{
    __shared__ float As[32][132];   // A^T: [k][m]
    __shared__ float Bs[32][68];    // B^T: [k][n]  (B row n = W row n)

    const float* Wm; const float* bias; float* outp;
    if (blockIdx.z == 0)      { Wm = Wq; bias = bq; outp = g_q; }
    else if (blockIdx.z == 1) { Wm = Wk; bias = bk; outp = g_k; }
    else                      { Wm = Wv; bias = bv; outp = g_v; }

    const int m0 = blockIdx.y * 128;
    const int n0 = blockIdx.x * 64;
    const int tid = threadIdx.x;
    const int tx = tid & 15, ty = tid >> 4;

    float acc[8][4];
    #pragma unroll
    for (int i = 0; i < 8; i++)
        #pragma unroll
        for (int j = 0; j < 4; j++) acc[i][j] = 0.f;

    for (int k0 = 0; k0 < 1024; k0 += 32) {
        __syncthreads();
        // load A tile: 128 rows x 32 k  (1024 float4)
        #pragma unroll
        for (int p = 0; p < 4; p++) {
            int idx = p * 256 + tid;
            int row = idx >> 3;
            int kv  = (idx & 7) * 4;
            float4 v = *(const float4*)&X[(size_t)(m0 + row) * 1024 + k0 + kv];
            As[kv + 0][row] = v.x; As[kv + 1][row] = v.y;
            As[kv + 2][row] = v.z; As[kv + 3][row] = v.w;
        }
        // load B tile: 64 rows (n) x 32 k (512 float4)
        #pragma unroll
        for (int p = 0; p < 2; p++) {
            int idx = p * 256 + tid;
            int row = idx >> 3;
            int kv  = (idx & 7) * 4;
            float4 v = *(const float4*)&Wm[(size_t)(n0 + row) * 1024 + k0 + kv];
            Bs[kv + 0][row] = v.x; Bs[kv + 1][row] = v.y;
            Bs[kv + 2][row] = v.z; Bs[kv + 3][row] = v.w;
        }
        __syncthreads();
        #pragma unroll
        for (int k = 0; k < 32; k++) {
            float4 a0 = *(const float4*)&As[k][ty * 8];
            float4 a1 = *(const float4*)&As[k][ty * 8 + 4];
            float4 b0 = *(const float4*)&Bs[k][tx * 4];
            float a[8] = {a0.x, a0.y, a0.z, a0.w, a1.x, a1.y, a1.z, a1.w};
            float b[4] = {b0.x, b0.y, b0.z, b0.w};
            #pragma unroll
            for (int i = 0; i < 8; i++)
                #pragma unroll
                for (int j = 0; j < 4; j++) acc[i][j] += a[i] * b[j];
        }
    }

    const int h = n0 >> 6;
    float4 bv4;
    bv4.x = bias[n0 + tx * 4 + 0]; bv4.y = bias[n0 + tx * 4 + 1];
    bv4.z = bias[n0 + tx * 4 + 2]; bv4.w = bias[n0 + tx * 4 + 3];
    #pragma unroll
    for (int i = 0; i < 8; i++) {
        int m = m0 + ty * 8 + i;
        int b_ = m >> 10, s = m & 1023;
        float4 r;
        r.x = acc[i][0] + bv4.x; r.y = acc[i][1] + bv4.y;
        r.z = acc[i][2] + bv4.z; r.w = acc[i][3] + bv4.w;
        *(float4*)&outp[(((size_t)(b_ * Hh + h)) * Ss + s) * Dd + tx * 4] = r;
    }
}

// ============================================================
// Kernel 2: hedgehog feature map.  y = W @ x + b; f = [exp(y), exp(-y)]
// grid.x over row groups of 128, grid.y = {q,k}
// ============================================================
__global__ __launch_bounds__(256) void feat_kernel(
    const float* __restrict__ Wfq, const float* __restrict__ bfq,
    const float* __restrict__ Wfk, const float* __restrict__ bfk)
{
    const float* Wf; const float* bf; const float* src; float* dst;
    if (blockIdx.y == 0) { Wf = Wfq; bf = bfq; src = g_q; dst = g_fq; }
    else                 { Wf = Wfk; bf = bfk; src = g_k; dst = g_fk; }

    __shared__ float Wt[64][65];   // Wt[d][e] = W[e][d]
    __shared__ float bsm[64];
    __shared__ float qs[4][64];

    const int tid = threadIdx.x;
    #pragma unroll
    for (int p = 0; p < 16; p++) {
        int idx = p * 256 + tid;
        Wt[idx & 63][idx >> 6] = Wf[idx];
    }
    if (tid < 64) bsm[tid] = bf[tid];

    const int rowbase = blockIdx.x * 128;
    const int e = tid & 63, rr = tid >> 6;

    for (int r0 = 0; r0 < 128; r0 += 4) {
        __syncthreads();
        int row = rowbase + r0 + rr;
        qs[rr][e] = src[(size_t)row * 64 + e];
        __syncthreads();
        float y = bsm[e];
        #pragma unroll
        for (int d = 0; d < 64; d++) y += Wt[d][e] * qs[rr][d];
        dst[(size_t)row * 128 + e]      = expf(y);
        dst[(size_t)row * 128 + 64 + e] = expf(-y);
    }
}

// ============================================================
// Kernel 3: true attention. One block per (bh, 64-row m-tile).
// Pass 1: raw scores -> out region, online max/sum.
// Pass 2: normalize in place + ctx = P@V accumulation.
// ============================================================
__global__ __launch_bounds__(256) void attn_true_kernel(float* __restrict__ outT)
{
    __shared__ float bufA[64][68];  // pass1: Q^T [d][m]; pass2: P^T [n][m]
    __shared__ float bufB[64][68];  // pass1: K^T [d][n]; pass2: V   [n][d]

    const int bh = blockIdx.y;
    const int m0 = blockIdx.x * 64;
    const int tid = threadIdx.x;
    const int tx = tid & 15, ty = tid >> 4;

    const float* qp = g_q + (size_t)bh * Ss * Dd;
    const float* kp = g_k + (size_t)bh * Ss * Dd;
    const float* vp = g_v + (size_t)bh * Ss * Dd;
    float* trow = outT + (size_t)bh * Ss * Ss;

    // load Q tile transposed
    #pragma unroll
    for (int p = 0; p < 4; p++) {
        int idx = p * 256 + tid;
        int row = idx >> 4;
        int c   = (idx & 15) * 4;
        float4 v = *(const float4*)&qp[(size_t)(m0 + row) * 64 + c];
        bufA[c + 0][row] = v.x; bufA[c + 1][row] = v.y;
        bufA[c + 2][row] = v.z; bufA[c + 3][row] = v.w;
    }

    float runmax[4], runsum[4];
    #pragma unroll
    for (int i = 0; i < 4; i++) { runmax[i] = -FLT_MAX; runsum[i] = 0.f; }

    // ---- pass 1 ----
    for (int nt = 0; nt < 16; nt++) {
        int n0 = nt * 64;
        __syncthreads();
        #pragma unroll
        for (int p = 0; p < 4; p++) {
            int idx = p * 256 + tid;
            int row = idx >> 4;
            int c   = (idx & 15) * 4;
            float4 v = *(const float4*)&kp[(size_t)(n0 + row) * 64 + c];
            bufB[c + 0][row] = v.x; bufB[c + 1][row] = v.y;
            bufB[c + 2][row] = v.z; bufB[c + 3][row] = v.w;
        }
        __syncthreads();

        float sc[4][4];
        #pragma unroll
        for (int i = 0; i < 4; i++)
            #pragma unroll
            for (int j = 0; j < 4; j++) sc[i][j] = 0.f;
        #pragma unroll
        for (int k = 0; k < 64; k++) {
            float4 a = *(const float4*)&bufA[k][ty * 4];
            float4 b = *(const float4*)&bufB[k][tx * 4];
            float av[4] = {a.x, a.y, a.z, a.w};
            float bvv[4] = {b.x, b.y, b.z, b.w};
            #pragma unroll
            for (int i = 0; i < 4; i++)
                #pragma unroll
                for (int j = 0; j < 4; j++) sc[i][j] += av[i] * bvv[j];
        }
        #pragma unroll
        for (int i = 0; i < 4; i++) {
            #pragma unroll
            for (int j = 0; j < 4; j++) sc[i][j] *= 0.125f;
            float tmax = fmaxf(fmaxf(sc[i][0], sc[i][1]), fmaxf(sc[i][2], sc[i][3]));
            #pragma unroll
            for (int off = 1; off < 16; off <<= 1)
                tmax = fmaxf(tmax, __shfl_xor_sync(0xffffffffu, tmax, off));
            float nm = fmaxf(runmax[i], tmax);
            float ps = __expf(sc[i][0] - nm) + __expf(sc[i][1] - nm)
                     + __expf(sc[i][2] - nm) + __expf(sc[i][3] - nm);
            #pragma unroll
            for (int off = 1; off < 16; off <<= 1)
                ps += __shfl_xor_sync(0xffffffffu, ps, off);
            runsum[i] = runsum[i] * __expf(runmax[i] - nm) + ps;
            runmax[i] = nm;
            float4 st = {sc[i][0], sc[i][1], sc[i][2], sc[i][3]};
            *(float4*)&trow[(size_t)(m0 + ty * 4 + i) * Ss + n0 + tx * 4] = st;
        }
    }

    float invs[4];
    #pragma unroll
    for (int i = 0; i < 4; i++) invs[i] = 1.f / runsum[i];

    // ---- pass 2 ----
    float cacc[4][4];
    #pragma unroll
    for (int i = 0; i < 4; i++)
        #pragma unroll
        for (int j = 0; j < 4; j++) cacc[i][j] = 0.f;

    for (int nt = 0; nt < 16; nt++) {
        int n0 = nt * 64;
        __syncthreads();
        // V tile, direct layout [n][d]
        #pragma unroll
        for (int p = 0; p < 4; p++) {
            int idx = p * 256 + tid;
            int row = idx >> 4;
            int c   = (idx & 15) * 4;
            float4 v = *(const float4*)&vp[(size_t)(n0 + row) * 64 + c];
            *(float4*)&bufB[row][c] = v;
        }
        // normalize raw scores in place + stage P^T in smem
        #pragma unroll
        for (int i = 0; i < 4; i++) {
            int m = m0 + ty * 4 + i;
            float4 sv = *(const float4*)&trow[(size_t)m * Ss + n0 + tx * 4];
            float4 pv;
            pv.x = __expf(sv.x - runmax[i]) * invs[i];
            pv.y = __expf(sv.y - runmax[i]) * invs[i];
            pv.z = __expf(sv.z - runmax[i]) * invs[i];
            pv.w = __expf(sv.w - runmax[i]) * invs[i];
            *(float4*)&trow[(size_t)m * Ss + n0 + tx * 4] = pv;
            bufA[tx * 4 + 0][ty * 4 + i] = pv.x;
            bufA[tx * 4 + 1][ty * 4 + i] = pv.y;
            bufA[tx * 4 + 2][ty * 4 + i] = pv.z;
            bufA[tx * 4 + 3][ty * 4 + i] = pv.w;
        }
        __syncthreads();
        #pragma unroll
        for (int k = 0; k < 64; k++) {
            float4 a = *(const float4*)&bufA[k][ty * 4];
            float4 b = *(const float4*)&bufB[k][tx * 4];
            float av[4] = {a.x, a.y, a.z, a.w};
            float bvv[4] = {b.x, b.y, b.z, b.w};
            #pragma unroll
            for (int i = 0; i < 4; i++)
                #pragma unroll
                for (int j = 0; j < 4; j++) cacc[i][j] += av[i] * bvv[j];
        }
    }

    float* cp = g_ctx + (size_t)bh * Ss * Dd;
    #pragma unroll
    for (int i = 0; i < 4; i++) {
        float4 r = {cacc[i][0], cacc[i][1], cacc[i][2], cacc[i][3]};
        *(float4*)&cp[(size_t)(m0 + ty * 4 + i) * 64 + tx * 4] = r;
    }
}

// ============================================================
// Kernel 4: hedgehog predicted attention.
// qk = fq @ fk^T (128-dim), raw -> out, then /rowsum in place.
// dynamic smem: Fq^T [128][68] + Fk^T [128][68]
// ============================================================
extern __shared__ float psm[];
__global__ __launch_bounds__(256) void attn_pred_kernel(float* __restrict__ outP)
{
    float* Fqs = psm;                 // [128][68]
    float* Fks = psm + 128 * 68;

    const int bh = blockIdx.y;
    const int m0 = blockIdx.x * 64;
    const int tid = threadIdx.x;
    const int tx = tid & 15, ty = tid >> 4;

    const float* fqp = g_fq + (size_t)bh * Ss * Ff;
    const float* fkp = g_fk + (size_t)bh * Ss * Ff;
    float* prow = outP + (size_t)bh * Ss * Ss;

    // load Fq tile transposed: 64 rows x 128
    #pragma unroll
    for (int p = 0; p < 8; p++) {
        int idx = p * 256 + tid;
        int row = idx >> 5;
        int c   = (idx & 31) * 4;
        float4 v = *(const float4*)&fqp[(size_t)(m0 + row) * 128 + c];
        Fqs[(c + 0) * 68 + row] = v.x; Fqs[(c + 1) * 68 + row] = v.y;
        Fqs[(c + 2) * 68 + row] = v.z; Fqs[(c + 3) * 68 + row] = v.w;
    }

    float rs[4] = {0.f, 0.f, 0.f, 0.f};

    for (int nt = 0; nt < 16; nt++) {
        int n0 = nt * 64;
        __syncthreads();
        #pragma unroll
        for (int p = 0; p < 8; p++) {
            int idx = p * 256 + tid;
            int row = idx >> 5;
            int c   = (idx & 31) * 4;
            float4 v = *(const float4*)&fkp[(size_t)(n0 + row) * 128 + c];
            Fks[(c + 0) * 68 + row] = v.x; Fks[(c + 1) * 68 + row] = v.y;
            Fks[(c + 2) * 68 + row] = v.z; Fks[(c + 3) * 68 + row] = v.w;
        }
        __syncthreads();

        float sc[4][4];
        #pragma unroll
        for (int i = 0; i < 4; i++)
            #pragma unroll
            for (int j = 0; j < 4; j++) sc[i][j] = 0.f;
        #pragma unroll
        for (int k = 0; k < 128; k++) {
            float4 a = *(const float4*)&Fqs[k * 68 + ty * 4];
            float4 b = *(const float4*)&Fks[k * 68 + tx * 4];
            float av[4] = {a.x, a.y, a.z, a.w};
            float bvv[4] = {b.x, b.y, b.z, b.w};
            #pragma unroll
            for (int i = 0; i < 4; i++)
                #pragma unroll
                for (int j = 0; j < 4; j++) sc[i][j] += av[i] * bvv[j];
        }
        #pragma unroll
        for (int i = 0; i < 4; i++) {
            rs[i] += sc[i][0] + sc[i][1] + sc[i][2] + sc[i][3];
            float4 st = {sc[i][0], sc[i][1], sc[i][2], sc[i][3]};
            *(float4*)&prow[(size_t)(m0 + ty * 4 + i) * Ss + n0 + tx * 4] = st;
        }
    }

    // reduce row sums across tx (16 lanes within half-warp)
    float inv[4];
    #pragma unroll
    for (int i = 0; i < 4; i++) {
        float v = rs[i];
        #pragma unroll
        for (int off = 1; off < 16; off <<= 1)
            v += __shfl_xor_sync(0xffffffffu, v, off);
        inv[i] = 1.f / v;
    }

    // normalize in place
    for (int nt = 0; nt < 16; nt++) {
        int n0 = nt * 64;
        #pragma unroll
        for (int i = 0; i < 4; i++) {
            size_t off = (size_t)(m0 + ty * 4 + i) * Ss + n0 + tx * 4;
            float4 v = *(const float4*)&prow[off];
            v.x *= inv[i]; v.y *= inv[i]; v.z *= inv[i]; v.w *= inv[i];
            *(float4*)&prow[off] = v;
        }
    }
}

// ============================================================
// Kernel 5: output projection. out = ctx_flat @ Wo^T + bo
// ============================================================
__global__ __launch_bounds__(256) void outproj_kernel(
    const float* __restrict__ Wo, const float* __restrict__ bo,
    float* __restrict__ out)
{
    __shared__ float As[32][132];
    __shared__ float Bs[32][68];

    const int m0 = blockIdx.y * 128;
    const int n0 = blockIdx.x * 64;
    const int tid = threadIdx.x;
    const int tx = tid & 15, ty = tid >> 4;

    float acc[8][4];
    #pragma unroll
    for (int i = 0; i < 8; i++)
        #pragma unroll
        for (int j = 0; j < 4; j++) acc[i][j] = 0.f;

    for (int k0 = 0; k0 < 1024; k0 += 32) {
        int h = k0 >> 6;          // k0 step 32 within 64-aligned head chunk
        int dbase = k0 & 63;
        __syncthreads();
        #pragma unroll
        for (int p = 0; p < 4; p++) {
            int idx = p * 256 + tid;
            int row = idx >> 3;
            int kv  = (idx & 7) * 4;
            int m = m0 + row;
            int b_ = m >> 10, s = m & 1023;
            float4 v = *(const float4*)&g_ctx[(((size_t)(b_ * Hh + h)) * Ss + s) * 64 + dbase + kv];
            As[kv + 0][row] = v.x; As[kv + 1][row] = v.y;
            As[kv + 2][row] = v.z; As[kv + 3][row] = v.w;
        }
        #pragma unroll
        for (int p = 0; p < 2; p++) {
            int idx = p * 256 + tid;
            int row = idx >> 3;
            int kv  = (idx & 7) * 4;
            float4 v = *(const float4*)&Wo[(size_t)(n0 + row) * 1024 + k0 + kv];
            Bs[kv + 0][row] = v.x; Bs[kv + 1][row] = v.y;
            Bs[kv + 2][row] = v.z; Bs[kv + 3][row] = v.w;
        }
        __syncthreads();
        #pragma unroll
        for (int k = 0; k < 32; k++) {
            float4 a0 = *(const float4*)&As[k][ty * 8];
            float4 a1 = *(const float4*)&As[k][ty * 8 + 4];
            float4 b0 = *(const float4*)&Bs[k][tx * 4];
            float a[8] = {a0.x, a0.y, a0.z, a0.w, a1.x, a1.y, a1.z, a1.w};
            float b[4] = {b0.x, b0.y, b0.z, b0.w};
            #pragma unroll
            for (int i = 0; i < 8; i++)
                #pragma unroll
                for (int j = 0; j < 4; j++) acc[i][j] += a[i] * b[j];
        }
    }

    float4 bv4;
    bv4.x = bo[n0 + tx * 4 + 0]; bv4.y = bo[n0 + tx * 4 + 1];
    bv4.z = bo[n0 + tx * 4 + 2]; bv4.w = bo[n0 + tx * 4 + 3];
    #pragma unroll
    for (int i = 0; i < 8; i++) {
        int m = m0 + ty * 8 + i;
        float4 r;
        r.x = acc[i][0] + bv4.x; r.y = acc[i][1] + bv4.y;
        r.z = acc[i][2] + bv4.z; r.w = acc[i][3] + bv4.w;
        *(float4*)&out[(size_t)m * 1024 + n0 + tx * 4] = r;
    }
}

// ============================================================
extern "C" void kernel_launch(void* const* d_in, const int* in_sizes, int n_in,
                              void* d_out, int out_size)
{
    const float* hs  = (const float*)d_in[0];
    const float* Wq  = (const float*)d_in[1];
    const float* bq  = (const float*)d_in[2];
    const float* Wk  = (const float*)d_in[3];
    const float* bk  = (const float*)d_in[4];
    const float* Wv  = (const float*)d_in[5];
    const float* bv  = (const float*)d_in[6];
    const float* Wo  = (const float*)d_in[7];
    const float* bo  = (const float*)d_in[8];
    const float* Wfq = (const float*)d_in[9];
    const float* bfq = (const float*)d_in[10];
    const float* Wfk = (const float*)d_in[11];
    const float* bfk = (const float*)d_in[12];
    float* out = (float*)d_out;

    cudaFuncSetAttribute(attn_pred_kernel,
                         cudaFuncAttributeMaxDynamicSharedMemorySize,
                         2 * 128 * 68 * (int)sizeof(float));

    qkv_kernel<<<dim3(16, 16, 3), 256>>>(hs, Wq, bq, Wk, bk, Wv, bv);
    feat_kernel<<<dim3(256, 2), 256>>>(Wfq, bfq, Wfk, bfk);
    attn_true_kernel<<<dim3(16, 32), 256>>>(out + OFF_TRUE);
    attn_pred_kernel<<<dim3(16, 32), 256, 2 * 128 * 68 * sizeof(float)>>>(out + OFF_PRED);
    outproj_kernel<<<dim3(16, 16), 256>>>(Wo, bo, out);
}

// round 2
// speedup vs baseline: 1.2620x; 1.2620x over previous
#include <cuda_runtime.h>
#include <math.h>

#define Bb 2
#define Ss 1024
#define DMm 1024
#define Hh 16
#define Dd 64
#define BH 32
#define Ff 128

typedef unsigned long long u64;

__device__ __forceinline__ u64 dup2(float x) {
    u64 r; asm("mov.b64 %0, {%1, %1};" : "=l"(r) : "f"(x)); return r;
}
__device__ __forceinline__ void fma2(u64 &d, u64 a, u64 b) {
    asm("fma.rn.f32x2 %0, %1, %2, %0;" : "+l"(d) : "l"(a), "l"(b));
}
__device__ __forceinline__ float2 up2(u64 v) {
    float2 f; asm("mov.b64 {%0, %1}, %2;" : "=f"(f.x), "=f"(f.y) : "l"(v)); return f;
}

// ---- scratch ----
__device__ float g_q[BH*Ss*Dd];
__device__ float g_k[BH*Ss*Dd];
__device__ float g_v[BH*Ss*Dd];
__device__ float g_fq[BH*Ss*Ff];
__device__ float g_fk[BH*Ss*Ff];
__device__ float g_ctx[BH*Ss*Dd];
__device__ float g_fks[BH*Ff];
__device__ float g_inv[BH*Ss];

#define OFF_PRED (Bb*Ss*DMm)
#define OFF_TRUE (OFF_PRED + BH*Ss*Ss)

extern __shared__ float dsm[];

// ============================================================
// Kernel 1: QKV projection. BM=128 BN=128 BK=32, 8x8/thread f32x2.
// ============================================================
__global__ __launch_bounds__(256, 2) void qkv_kernel(
    const float* __restrict__ X,
    const float* __restrict__ Wq, const float* __restrict__ bq,
    const float* __restrict__ Wk, const float* __restrict__ bk,
    const float* __restrict__ Wv, const float* __restrict__ bv)
{
    __shared__ __align__(16) float As[32][132];
    __shared__ __align__(16) float Bs[32][132];

    const float* Wm; const float* bias; float* outp;
    if (blockIdx.z == 0)      { Wm = Wq; bias = bq; outp = g_q; }
    else if (blockIdx.z == 1) { Wm = Wk; bias = bk; outp = g_k; }
    else                      { Wm = Wv; bias = bv; outp = g_v; }

    const int m0 = blockIdx.y * 128, n0 = blockIdx.x * 128;
    const int tid = threadIdx.x, tx = tid & 15, ty = tid >> 4;

    u64 acc[4][8];
    #pragma unroll
    for (int p = 0; p < 4; p++)
        #pragma unroll
        for (int j = 0; j < 8; j++) acc[p][j] = 0ull;

    for (int k0 = 0; k0 < 1024; k0 += 32) {
        __syncthreads();
        #pragma unroll
        for (int p = 0; p < 4; p++) {
            int idx = p * 256 + tid;
            int row = idx >> 3, kc = (idx & 7) * 4;
            float4 v = *(const float4*)&X[(size_t)(m0 + row) * 1024 + k0 + kc];
            As[kc][row] = v.x; As[kc+1][row] = v.y; As[kc+2][row] = v.z; As[kc+3][row] = v.w;
        }
        #pragma unroll
        for (int p = 0; p < 4; p++) {
            int idx = p * 256 + tid;
            int row = idx >> 3, kc = (idx & 7) * 4;
            float4 v = *(const float4*)&Wm[(size_t)(n0 + row) * 1024 + k0 + kc];
            Bs[kc][row] = v.x; Bs[kc+1][row] = v.y; Bs[kc+2][row] = v.z; Bs[kc+3][row] = v.w;
        }
        __syncthreads();
        #pragma unroll 8
        for (int k = 0; k < 32; k++) {
            ulonglong2 a0 = *(const ulonglong2*)&As[k][ty * 8];
            ulonglong2 a1 = *(const ulonglong2*)&As[k][ty * 8 + 4];
            u64 ap[4] = {a0.x, a0.y, a1.x, a1.y};
            float4 b0 = *(const float4*)&Bs[k][tx * 4];
            float4 b1 = *(const float4*)&Bs[k][tx * 4 + 64];
            u64 bd[8] = {dup2(b0.x), dup2(b0.y), dup2(b0.z), dup2(b0.w),
                         dup2(b1.x), dup2(b1.y), dup2(b1.z), dup2(b1.w)};
            #pragma unroll
            for (int p = 0; p < 4; p++)
                #pragma unroll
                for (int j = 0; j < 8; j++) fma2(acc[p][j], ap[p], bd[j]);
        }
    }

    float4 bv0 = *(const float4*)&bias[n0 + tx * 4];
    float4 bv1 = *(const float4*)&bias[n0 + 64 + tx * 4];
    const int na = n0 + tx * 4, nb = n0 + 64 + tx * 4;
    const int ha = na >> 6, hb = nb >> 6;
    #pragma unroll
    for (int p = 0; p < 4; p++) {
        float2 c[8];
        #pragma unroll
        for (int j = 0; j < 8; j++) c[j] = up2(acc[p][j]);
        int m = m0 + ty * 8 + 2 * p;
        int b_ = m >> 10, s = m & 1023;
        float4 r;
        r.x = c[0].x + bv0.x; r.y = c[1].x + bv0.y; r.z = c[2].x + bv0.z; r.w = c[3].x + bv0.w;
        *(float4*)&outp[(((size_t)(b_ * Hh + ha)) * Ss + s) * Dd + (na & 63)] = r;
        r.x = c[4].x + bv1.x; r.y = c[5].x + bv1.y; r.z = c[6].x + bv1.z; r.w = c[7].x + bv1.w;
        *(float4*)&outp[(((size_t)(b_ * Hh + hb)) * Ss + s) * Dd + (nb & 63)] = r;
        r.x = c[0].y + bv0.x; r.y = c[1].y + bv0.y; r.z = c[2].y + bv0.z; r.w = c[3].y + bv0.w;
        *(float4*)&outp[(((size_t)(b_ * Hh + ha)) * Ss + s + 1) * Dd + (na & 63)] = r;
        r.x = c[4].y + bv1.x; r.y = c[5].y + bv1.y; r.z = c[6].y + bv1.z; r.w = c[7].y + bv1.w;
        *(float4*)&outp[(((size_t)(b_ * Hh + hb)) * Ss + s + 1) * Dd + (nb & 63)] = r;
    }
}

// ============================================================
// Kernel 2: hedgehog feature map (unchanged structure).
// ============================================================
__global__ __launch_bounds__(256) void feat_kernel(
    const float* __restrict__ Wfq, const float* __restrict__ bfq,
    const float* __restrict__ Wfk, const float* __restrict__ bfk)
{
    const float* Wf; const float* bf; const float* src; float* dst;
    if (blockIdx.y == 0) { Wf = Wfq; bf = bfq; src = g_q; dst = g_fq; }
    else                 { Wf = Wfk; bf = bfk; src = g_k; dst = g_fk; }

    __shared__ float Wt[64][65];
    __shared__ float bsm[64];
    __shared__ float qs[4][64];

    const int tid = threadIdx.x;
    #pragma unroll
    for (int p = 0; p < 16; p++) {
        int idx = p * 256 + tid;
        Wt[idx & 63][idx >> 6] = Wf[idx];
    }
    if (tid < 64) bsm[tid] = bf[tid];

    const int rowbase = blockIdx.x * 128;
    const int e = tid & 63, rr = tid >> 6;

    for (int r0 = 0; r0 < 128; r0 += 4) {
        __syncthreads();
        int row = rowbase + r0 + rr;
        qs[rr][e] = src[(size_t)row * 64 + e];
        __syncthreads();
        float y = bsm[e];
        #pragma unroll
        for (int d = 0; d < 64; d++) y += Wt[d][e] * qs[rr][d];
        dst[(size_t)row * 128 + e]      = expf(y);
        dst[(size_t)row * 128 + 64 + e] = expf(-y);
    }
}

// ============================================================
// Kernel 3: fk column sums per head:  fksum[bh][e] = sum_s fk[bh][s][e]
// ============================================================
__global__ __launch_bounds__(256) void fksum_kernel()
{
    const int bh = blockIdx.x, tid = threadIdx.x;
    const int e = tid & 127, part = tid >> 7;
    const float* fkp = g_fk + (size_t)bh * Ss * Ff;
    float s = 0.f;
    for (int r = part; r < 1024; r += 2) s += fkp[(size_t)r * 128 + e];
    __shared__ float sm[256];
    sm[tid] = s;
    __syncthreads();
    if (tid < 128) g_fks[bh * 128 + tid] = sm[tid] + sm[tid + 128];
}

// ============================================================
// Kernel 4: true attention pass 1: P = exp(QK^T/8) -> out, rowsum -> g_inv.
// BM=128 BN=128 K=64. dyn smem: Qs[64][132] + Ks[64][132].
// ============================================================
__global__ __launch_bounds__(256, 2) void true_exp_kernel(float* __restrict__ outT)
{
    float* Qs = dsm;            // [64][132] (Q^T, prescaled by 1/8)
    float* Ks = dsm + 64 * 132; // [64][132]

    const int bh = blockIdx.y, m0 = blockIdx.x * 128;
    const int tid = threadIdx.x, tx = tid & 15, ty = tid >> 4;

    const float* qp = g_q + (size_t)bh * Ss * Dd;
    const float* kp = g_k + (size_t)bh * Ss * Dd;
    float* trow = outT + (size_t)bh * Ss * Ss;

    #pragma unroll
    for (int p = 0; p < 8; p++) {
        int idx = p * 256 + tid;
        int row = idx >> 4, c = (idx & 15) * 4;
        float4 v = *(const float4*)&qp[(size_t)(m0 + row) * 64 + c];
        Qs[(c+0)*132 + row] = v.x * 0.125f; Qs[(c+1)*132 + row] = v.y * 0.125f;
        Qs[(c+2)*132 + row] = v.z * 0.125f; Qs[(c+3)*132 + row] = v.w * 0.125f;
    }

    float rsum[8];
    #pragma unroll
    for (int i = 0; i < 8; i++) rsum[i] = 0.f;

    for (int nt = 0; nt < 8; nt++) {
        const int n0 = nt * 128;
        __syncthreads();
        #pragma unroll
        for (int p = 0; p < 8; p++) {
            int idx = p * 256 + tid;
            int row = idx >> 4, c = (idx & 15) * 4;
            float4 v = *(const float4*)&kp[(size_t)(n0 + row) * 64 + c];
            Ks[(c+0)*132 + row] = v.x; Ks[(c+1)*132 + row] = v.y;
            Ks[(c+2)*132 + row] = v.z; Ks[(c+3)*132 + row] = v.w;
        }
        __syncthreads();

        u64 acc[4][8];
        #pragma unroll
        for (int p = 0; p < 4; p++)
            #pragma unroll
            for (int j = 0; j < 8; j++) acc[p][j] = 0ull;

        #pragma unroll 8
        for (int k = 0; k < 64; k++) {
            ulonglong2 a0 = *(const ulonglong2*)&Qs[k * 132 + ty * 8];
            ulonglong2 a1 = *(const ulonglong2*)&Qs[k * 132 + ty * 8 + 4];
            u64 ap[4] = {a0.x, a0.y, a1.x, a1.y};
            float4 b0 = *(const float4*)&Ks[k * 132 + tx * 4];
            float4 b1 = *(const float4*)&Ks[k * 132 + tx * 4 + 64];
            u64 bd[8] = {dup2(b0.x), dup2(b0.y), dup2(b0.z), dup2(b0.w),
                         dup2(b1.x), dup2(b1.y), dup2(b1.z), dup2(b1.w)};
            #pragma unroll
            for (int p = 0; p < 4; p++)
                #pragma unroll
                for (int j = 0; j < 8; j++) fma2(acc[p][j], ap[p], bd[j]);
        }

        #pragma unroll
        for (int p = 0; p < 4; p++) {
            float2 c[8];
            #pragma unroll
            for (int j = 0; j < 8; j++) c[j] = up2(acc[p][j]);
            float e0[8], e1[8];
            #pragma unroll
            for (int j = 0; j < 8; j++) { e0[j] = __expf(c[j].x); e1[j] = __expf(c[j].y); }
            rsum[2*p]   += e0[0]+e0[1]+e0[2]+e0[3]+e0[4]+e0[5]+e0[6]+e0[7];
            rsum[2*p+1] += e1[0]+e1[1]+e1[2]+e1[3]+e1[4]+e1[5]+e1[6]+e1[7];
            size_t r0 = (size_t)(m0 + ty * 8 + 2 * p) * 1024 + n0;
            *(float4*)&trow[r0 + tx * 4]        = make_float4(e0[0], e0[1], e0[2], e0[3]);
            *(float4*)&trow[r0 + 64 + tx * 4]   = make_float4(e0[4], e0[5], e0[6], e0[7]);
            *(float4*)&trow[r0 + 1024 + tx * 4]      = make_float4(e1[0], e1[1], e1[2], e1[3]);
            *(float4*)&trow[r0 + 1024 + 64 + tx * 4] = make_float4(e1[4], e1[5], e1[6], e1[7]);
        }
    }

    #pragma unroll
    for (int i = 0; i < 8; i++) {
        float v = rsum[i];
        #pragma unroll
        for (int off = 1; off < 16; off <<= 1)
            v += __shfl_xor_sync(0xffffffffu, v, off);
        if (tx == 0) g_inv[bh * 1024 + m0 + ty * 8 + i] = 1.f / v;
    }
}

// ============================================================
// Kernel 5: hedgehog pred, one pass. denom via fq . fksum.
// BM=128 BN=128 K=128 (Fk staged in two 64-k chunks -> 2 blocks/SM).
// dyn smem: FqT[128][132] + FkT[64][132]
// ============================================================
__global__ __launch_bounds__(256, 2) void pred_kernel(float* __restrict__ outP)
{
    float* FqT = dsm;             // [128 k][132]
    float* FkT = dsm + 128 * 132; // [64 k][132]
    __shared__ float fks[128];
    __shared__ float invsm[128];

    const int bh = blockIdx.y, m0 = blockIdx.x * 128;
    const int tid = threadIdx.x, tx = tid & 15, ty = tid >> 4;

    const float* fqp = g_fq + (size_t)bh * Ss * Ff;
    const float* fkp = g_fk + (size_t)bh * Ss * Ff;
    float* prow = outP + (size_t)bh * Ss * Ss;

    if (tid < 128) fks[tid] = g_fks[bh * 128 + tid];

    #pragma unroll
    for (int p = 0; p < 16; p++) {
        int idx = p * 256 + tid;
        int row = idx >> 5, c = (idx & 31) * 4;
        float4 v = *(const float4*)&fqp[(size_t)(m0 + row) * 128 + c];
        FqT[(c+0)*132 + row] = v.x; FqT[(c+1)*132 + row] = v.y;
        FqT[(c+2)*132 + row] = v.z; FqT[(c+3)*132 + row] = v.w;
    }
    __syncthreads();

    if (tid < 128) {
        float s = 0.f;
        #pragma unroll 8
        for (int k = 0; k < 128; k++) s += FqT[k * 132 + tid] * fks[k];
        invsm[tid] = 1.f / s;
    }
    __syncthreads();

    float invr[8];
    #pragma unroll
    for (int i = 0; i < 8; i++) invr[i] = invsm[ty * 8 + i];

    for (int nt = 0; nt < 8; nt++) {
        const int n0 = nt * 128;
        u64 acc[4][8];
        #pragma unroll
        for (int p = 0; p < 4; p++)
            #pragma unroll
            for (int j = 0; j < 8; j++) acc[p][j] = 0ull;

        #pragma unroll
        for (int half = 0; half < 2; half++) {
            __syncthreads();
            #pragma unroll
            for (int p = 0; p < 8; p++) {
                int idx = p * 256 + tid;
                int row = idx >> 4, c = (idx & 15) * 4;   // row: n (0..127), c: k (0..60)
                float4 v = *(const float4*)&fkp[(size_t)(n0 + row) * 128 + half * 64 + c];
                FkT[(c+0)*132 + row] = v.x; FkT[(c+1)*132 + row] = v.y;
                FkT[(c+2)*132 + row] = v.z; FkT[(c+3)*132 + row] = v.w;
            }
            __syncthreads();
            #pragma unroll 8
            for (int kk = 0; kk < 64; kk++) {
                int kg = half * 64 + kk;
                ulonglong2 a0 = *(const ulonglong2*)&FqT[kg * 132 + ty * 8];
                ulonglong2 a1 = *(const ulonglong2*)&FqT[kg * 132 + ty * 8 + 4];
                u64 ap[4] = {a0.x, a0.y, a1.x, a1.y};
                float4 b0 = *(const float4*)&FkT[kk * 132 + tx * 4];
                float4 b1 = *(const float4*)&FkT[kk * 132 + tx * 4 + 64];
                u64 bd[8] = {dup2(b0.x), dup2(b0.y), dup2(b0.z), dup2(b0.w),
                             dup2(b1.x), dup2(b1.y), dup2(b1.z), dup2(b1.w)};
                #pragma unroll
                for (int p = 0; p < 4; p++)
                    #pragma unroll
                    for (int j = 0; j < 8; j++) fma2(acc[p][j], ap[p], bd[j]);
            }
        }

        #pragma unroll
        for (int p = 0; p < 4; p++) {
            float2 c[8];
            #pragma unroll
            for (int j = 0; j < 8; j++) c[j] = up2(acc[p][j]);
            float i0 = invr[2*p], i1 = invr[2*p+1];
            size_t r0 = (size_t)(m0 + ty * 8 + 2 * p) * 1024 + n0;
            *(float4*)&prow[r0 + tx * 4]      = make_float4(c[0].x*i0, c[1].x*i0, c[2].x*i0, c[3].x*i0);
            *(float4*)&prow[r0 + 64 + tx * 4] = make_float4(c[4].x*i0, c[5].x*i0, c[6].x*i0, c[7].x*i0);
            *(float4*)&prow[r0 + 1024 + tx * 4]      = make_float4(c[0].y*i1, c[1].y*i1, c[2].y*i1, c[3].y*i1);
            *(float4*)&prow[r0 + 1024 + 64 + tx * 4] = make_float4(c[4].y*i1, c[5].y*i1, c[6].y*i1, c[7].y*i1);
        }
    }
}

// ============================================================
// Kernel 6: ctx = Pnorm @ V, normalizing trow in place while loading.
// BM=128 BN=64(=Dd) BK=32, 8x4/thread f32x2.
// ============================================================
__global__ __launch_bounds__(256, 2) void ctx_kernel(float* __restrict__ outT)
{
    __shared__ __align__(16) float As[32][132];
    __shared__ __align__(16) float Bs[32][68];
    __shared__ float invsm[128];

    const int bh = blockIdx.y, m0 = blockIdx.x * 128;
    const int tid = threadIdx.x, tx = tid & 15, ty = tid >> 4;

    float* trow = outT + (size_t)bh * Ss * Ss;
    const float* vp = g_v + (size_t)bh * Ss * Dd;

    if (tid < 128) invsm[tid] = g_inv[bh * 1024 + m0 + tid];
    __syncthreads();

    u64 acc[4][4];
    #pragma unroll
    for (int p = 0; p < 4; p++)
        #pragma unroll
        for (int j = 0; j < 4; j++) acc[p][j] = 0ull;

    for (int k0 = 0; k0 < 1024; k0 += 32) {
        __syncthreads();
        #pragma unroll
        for (int p = 0; p < 4; p++) {
            int idx = p * 256 + tid;
            int row = idx >> 3, kc = (idx & 7) * 4;
            size_t ga = (size_t)(m0 + row) * 1024 + k0 + kc;
            float4 v = *(const float4*)&trow[ga];
            float iv = invsm[row];
            v.x *= iv; v.y *= iv; v.z *= iv; v.w *= iv;
            *(float4*)&trow[ga] = v;                 // normalized write-back
            As[kc][row] = v.x; As[kc+1][row] = v.y; As[kc+2][row] = v.z; As[kc+3][row] = v.w;
        }
        #pragma unroll
        for (int p = 0; p < 2; p++) {
            int idx = p * 256 + tid;
            int row = idx >> 4, c = (idx & 15) * 4;
            *(float4*)&Bs[row][c] = *(const float4*)&vp[(size_t)(k0 + row) * 64 + c];
        }
        __syncthreads();
        #pragma unroll 8
        for (int k = 0; k < 32; k++) {
            ulonglong2 a0 = *(const ulonglong2*)&As[k][ty * 8];
            ulonglong2 a1 = *(const ulonglong2*)&As[k][ty * 8 + 4];
            u64 ap[4] = {a0.x, a0.y, a1.x, a1.y};
            float4 b = *(const float4*)&Bs[k][tx * 4];
            u64 bd[4] = {dup2(b.x), dup2(b.y), dup2(b.z), dup2(b.w)};
            #pragma unroll
            for (int p = 0; p < 4; p++)
                #pragma unroll
                for (int j = 0; j < 4; j++) fma2(acc[p][j], ap[p], bd[j]);
        }
    }

    float* cp = g_ctx + (size_t)bh * Ss * Dd;
    #pragma unroll
    for (int p = 0; p < 4; p++) {
        float2 c0 = up2(acc[p][0]), c1 = up2(acc[p][1]), c2 = up2(acc[p][2]), c3 = up2(acc[p][3]);
        int m = m0 + ty * 8 + 2 * p;
        *(float4*)&cp[(size_t)m * 64 + tx * 4]       = make_float4(c0.x, c1.x, c2.x, c3.x);
        *(float4*)&cp[(size_t)(m + 1) * 64 + tx * 4] = make_float4(c0.y, c1.y, c2.y, c3.y);
    }
}

// ============================================================
// Kernel 7: output projection. Same shape as qkv, A from g_ctx head layout.
// ============================================================
__global__ __launch_bounds__(256, 2) void outproj_kernel(
    const float* __restrict__ Wo, const float* __restrict__ bo,
    float* __restrict__ out)
{
    __shared__ __align__(16) float As[32][132];
    __shared__ __align__(16) float Bs[32][132];

    const int m0 = blockIdx.y * 128, n0 = blockIdx.x * 128;
    const int tid = threadIdx.x, tx = tid & 15, ty = tid >> 4;

    u64 acc[4][8];
    #pragma unroll
    for (int p = 0; p < 4; p++)
        #pragma unroll
        for (int j = 0; j < 8; j++) acc[p][j] = 0ull;

    for (int k0 = 0; k0 < 1024; k0 += 32) {
        const int h = k0 >> 6, dbase = k0 & 63;
        __syncthreads();
        #pragma unroll
        for (int p = 0; p < 4; p++) {
            int idx = p * 256 + tid;
            int row = idx >> 3, kc = (idx & 7) * 4;
            int m = m0 + row;
            int b_ = m >> 10, s = m & 1023;
            float4 v = *(const float4*)&g_ctx[(((size_t)(b_ * Hh + h)) * Ss + s) * 64 + dbase + kc];
            As[kc][row] = v.x; As[kc+1][row] = v.y; As[kc+2][row] = v.z; As[kc+3][row] = v.w;
        }
        #pragma unroll
        for (int p = 0; p < 4; p++) {
            int idx = p * 256 + tid;
            int row = idx >> 3, kc = (idx & 7) * 4;
            float4 v = *(const float4*)&Wo[(size_t)(n0 + row) * 1024 + k0 + kc];
            Bs[kc][row] = v.x; Bs[kc+1][row] = v.y; Bs[kc+2][row] = v.z; Bs[kc+3][row] = v.w;
        }
        __syncthreads();
        #pragma unroll 8
        for (int k = 0; k < 32; k++) {
            ulonglong2 a0 = *(const ulonglong2*)&As[k][ty * 8];
            ulonglong2 a1 = *(const ulonglong2*)&As[k][ty * 8 + 4];
            u64 ap[4] = {a0.x, a0.y, a1.x, a1.y};
            float4 b0 = *(const float4*)&Bs[k][tx * 4];
            float4 b1 = *(const float4*)&Bs[k][tx * 4 + 64];
            u64 bd[8] = {dup2(b0.x), dup2(b0.y), dup2(b0.z), dup2(b0.w),
                         dup2(b1.x), dup2(b1.y), dup2(b1.z), dup2(b1.w)};
            #pragma unroll
            for (int p = 0; p < 4; p++)
                #pragma unroll
                for (int j = 0; j < 8; j++) fma2(acc[p][j], ap[p], bd[j]);
        }
    }

    float4 bv0 = *(const float4*)&bo[n0 + tx * 4];
    float4 bv1 = *(const float4*)&bo[n0 + 64 + tx * 4];
    #pragma unroll
    for (int p = 0; p < 4; p++) {
        float2 c[8];
        #pragma unroll
        for (int j = 0; j < 8; j++) c[j] = up2(acc[p][j]);
        size_t m = (size_t)(m0 + ty * 8 + 2 * p);
        *(float4*)&out[m * 1024 + n0 + tx * 4] =
            make_float4(c[0].x + bv0.x, c[1].x + bv0.y, c[2].x + bv0.z, c[3].x + bv0.w);
        *(float4*)&out[m * 1024 + n0 + 64 + tx * 4] =
            make_float4(c[4].x + bv1.x, c[5].x + bv1.y, c[6].x + bv1.z, c[7].x + bv1.w);
        *(float4*)&out[(m + 1) * 1024 + n0 + tx * 4] =
            make_float4(c[0].y + bv0.x, c[1].y + bv0.y, c[2].y + bv0.z, c[3].y + bv0.w);
        *(float4*)&out[(m + 1) * 1024 + n0 + 64 + tx * 4] =
            make_float4(c[4].y + bv1.x, c[5].y + bv1.y, c[6].y + bv1.z, c[7].y + bv1.w);
    }
}

// ============================================================
extern "C" void kernel_launch(void* const* d_in, const int* in_sizes, int n_in,
                              void* d_out, int out_size)
{
    const float* hs  = (const float*)d_in[0];
    const float* Wq  = (const float*)d_in[1];
    const float* bq  = (const float*)d_in[2];
    const float* Wk  = (const float*)d_in[3];
    const float* bk  = (const float*)d_in[4];
    const float* Wv  = (const float*)d_in[5];
    const float* bv  = (const float*)d_in[6];
    const float* Wo  = (const float*)d_in[7];
    const float* bo  = (const float*)d_in[8];
    const float* Wfq = (const float*)d_in[9];
    const float* bfq = (const float*)d_in[10];
    const float* Wfk = (const float*)d_in[11];
    const float* bfk = (const float*)d_in[12];
    float* out = (float*)d_out;

    const int smem_true = 2 * 64 * 132 * (int)sizeof(float);        // 67584
    const int smem_pred = (128 + 64) * 132 * (int)sizeof(float);    // 101376
    cudaFuncSetAttribute(true_exp_kernel, cudaFuncAttributeMaxDynamicSharedMemorySize, smem_true);
    cudaFuncSetAttribute(pred_kernel,     cudaFuncAttributeMaxDynamicSharedMemorySize, smem_pred);

    qkv_kernel<<<dim3(8, 16, 3), 256>>>(hs, Wq, bq, Wk, bk, Wv, bv);
    feat_kernel<<<dim3(256, 2), 256>>>(Wfq, bfq, Wfk, bfk);
    fksum_kernel<<<32, 256>>>();
    true_exp_kernel<<<dim3(8, 32), 256, smem_true>>>(out + OFF_TRUE);
    pred_kernel<<<dim3(8, 32), 256, smem_pred>>>(out + OFF_PRED);
    ctx_kernel<<<dim3(8, 32), 256>>>(out + OFF_TRUE);
    outproj_kernel<<<dim3(8, 16), 256>>>(Wo, bo, out);
}